// round 15
// baseline (speedup 1.0000x reference)
#include <cuda_runtime.h>
#include <cstdint>

// Problem constants (fixed shapes for this dataset)
#define NNODES   50000
#define DFEAT    256
#define H1HEADS  4
#define NGRAPHS  8
#define EMAX     400000
#define ETOTMAX  (EMAX + NNODES)

// ---------------- scratch (static device globals; no allocation) ----------------
__device__ float g_bufA[NNODES * DFEAT];   // linear-layer output (h1 / h2)
__device__ float g_bufB[NNODES * DFEAT];   // aggregation output
__device__ float g_als1[NNODES * H1HEADS];
__device__ float g_ald1[NNODES * H1HEADS];
__device__ float g_als2[NNODES];
__device__ float g_ald2[NNODES];
__device__ int   g_cnt[NNODES + 1];
__device__ int   g_rowst[NNODES + 1];
__device__ int   g_cursor[NNODES];
__device__ int   g_src_sorted[ETOTMAX];
__device__ float g_bn_sum[DFEAT];
__device__ float g_bn_sumsq[DFEAT];
__device__ float g_sc1[DFEAT];
__device__ float g_sh1[DFEAT];
__device__ float g_sc2[DFEAT];
__device__ float g_sh2[DFEAT];
__device__ float g_pool_sum[NGRAPHS * DFEAT];
__device__ float g_s2[NGRAPHS];

static inline int cdiv(int a, int b) { return (a + b - 1) / b; }

// ---------------- tf32 helpers ----------------
__device__ __forceinline__ uint32_t f2tf32(float x) {
    uint32_t u;
    asm("cvt.rna.tf32.f32 %0, %1;" : "=r"(u) : "f"(x));
    return u;
}

__device__ __forceinline__ void mma_tf32(float* d, const uint32_t* a, const uint32_t* b) {
    asm volatile(
        "mma.sync.aligned.m16n8k8.row.col.f32.tf32.tf32.f32 "
        "{%0,%1,%2,%3}, {%4,%5,%6,%7}, {%8,%9}, {%0,%1,%2,%3};"
        : "+f"(d[0]), "+f"(d[1]), "+f"(d[2]), "+f"(d[3])
        : "r"(a[0]), "r"(a[1]), "r"(a[2]), "r"(a[3]), "r"(b[0]), "r"(b[1]));
}

// ---------------- tf32 MMA GEMM: 128x128 block, warps 4x2 (each 32x64) ----------
// ALH: 0=no attention epilogue, 1=single-head (layer2), 4=4-head (layer1; each
// warp's 64-col span lies in exactly one head: head=(n0+wn)>>6).
// BNA: y=relu(a*sc[k]+sh[k]) applied per channel on A load.
#define MTK 16
template <bool BNA, int ALH>
__global__ __launch_bounds__(256) void mma_gemm_k(
        const float* __restrict__ A, const float* __restrict__ B,
        float* __restrict__ C, int M, int K, int Nn,
        const float* __restrict__ sc, const float* __restrict__ sh,
        const float* __restrict__ asrc, const float* __restrict__ adst,
        float* __restrict__ als, float* __restrict__ ald) {
    __shared__ uint32_t As[MTK][128 + 8];
    __shared__ uint32_t Bs[MTK][128 + 8];
    int t    = threadIdx.x;
    int lane = t & 31;
    int wid  = t >> 5;
    int wm   = (wid >> 1) * 32;
    int wn   = (wid & 1) * 64;
    int m0   = blockIdx.y * 128;
    int n0   = blockIdx.x * 128;
    int g    = lane >> 2;
    int t4   = lane & 3;

    float acc[2][8][4];
#pragma unroll
    for (int mt = 0; mt < 2; mt++)
#pragma unroll
        for (int nt = 0; nt < 8; nt++)
#pragma unroll
            for (int i = 0; i < 4; i++) acc[mt][nt][i] = 0.f;

    for (int k0 = 0; k0 < K; k0 += MTK) {
#pragma unroll
        for (int i = 0; i < 2; i++) {
            int f  = t + i * 256;
            int r  = f >> 2;
            int c4 = (f & 3) * 4;
            int gm = m0 + r;
            float4 v = make_float4(0.f, 0.f, 0.f, 0.f);
            if (gm < M) v = *(const float4*)(A + (size_t)gm * K + k0 + c4);
            if (BNA) {
                v.x = fmaxf(v.x * sc[k0 + c4 + 0] + sh[k0 + c4 + 0], 0.f);
                v.y = fmaxf(v.y * sc[k0 + c4 + 1] + sh[k0 + c4 + 1], 0.f);
                v.z = fmaxf(v.z * sc[k0 + c4 + 2] + sh[k0 + c4 + 2], 0.f);
                v.w = fmaxf(v.w * sc[k0 + c4 + 3] + sh[k0 + c4 + 3], 0.f);
            }
            As[c4 + 0][r] = f2tf32(v.x); As[c4 + 1][r] = f2tf32(v.y);
            As[c4 + 2][r] = f2tf32(v.z); As[c4 + 3][r] = f2tf32(v.w);
        }
#pragma unroll
        for (int i = 0; i < 2; i++) {
            int f  = t + i * 256;
            int r  = f >> 5;
            int c4 = (f & 31) * 4;
            float4 v = *(const float4*)(B + (size_t)(k0 + r) * Nn + n0 + c4);
            Bs[r][c4 + 0] = f2tf32(v.x); Bs[r][c4 + 1] = f2tf32(v.y);
            Bs[r][c4 + 2] = f2tf32(v.z); Bs[r][c4 + 3] = f2tf32(v.w);
        }
        __syncthreads();
#pragma unroll
        for (int ks = 0; ks < MTK; ks += 8) {
            uint32_t af[2][4];
#pragma unroll
            for (int mt = 0; mt < 2; mt++) {
                int mr = wm + mt * 16;
                af[mt][0] = As[ks + t4][mr + g];
                af[mt][1] = As[ks + t4][mr + g + 8];
                af[mt][2] = As[ks + t4 + 4][mr + g];
                af[mt][3] = As[ks + t4 + 4][mr + g + 8];
            }
            uint32_t bf[8][2];
#pragma unroll
            for (int nt = 0; nt < 8; nt++) {
                int nc = wn + nt * 8 + g;
                bf[nt][0] = Bs[ks + t4][nc];
                bf[nt][1] = Bs[ks + t4 + 4][nc];
            }
#pragma unroll
            for (int mt = 0; mt < 2; mt++)
#pragma unroll
                for (int nt = 0; nt < 8; nt++)
                    mma_tf32(acc[mt][nt], af[mt], bf[nt]);
        }
        __syncthreads();
    }

#pragma unroll
    for (int mt = 0; mt < 2; mt++) {
        int gm0 = m0 + wm + mt * 16 + g;
        int gm1 = gm0 + 8;
        float s0 = 0.f, d0 = 0.f, s1 = 0.f, d1 = 0.f;
#pragma unroll
        for (int nt = 0; nt < 8; nt++) {
            int cb = n0 + wn + nt * 8 + 2 * t4;
            if (gm0 < M)
                *(float2*)(C + (size_t)gm0 * Nn + cb) = make_float2(acc[mt][nt][0], acc[mt][nt][1]);
            if (gm1 < M)
                *(float2*)(C + (size_t)gm1 * Nn + cb) = make_float2(acc[mt][nt][2], acc[mt][nt][3]);
            if (ALH) {
                float w0s = asrc[cb], w1s = asrc[cb + 1];
                float w0d = adst[cb], w1d = adst[cb + 1];
                s0 += acc[mt][nt][0] * w0s + acc[mt][nt][1] * w1s;
                d0 += acc[mt][nt][0] * w0d + acc[mt][nt][1] * w1d;
                s1 += acc[mt][nt][2] * w0s + acc[mt][nt][3] * w1s;
                d1 += acc[mt][nt][2] * w0d + acc[mt][nt][3] * w1d;
            }
        }
        if (ALH) {
#pragma unroll
            for (int o = 2; o; o >>= 1) {
                s0 += __shfl_down_sync(0xffffffffu, s0, o, 4);
                d0 += __shfl_down_sync(0xffffffffu, d0, o, 4);
                s1 += __shfl_down_sync(0xffffffffu, s1, o, 4);
                d1 += __shfl_down_sync(0xffffffffu, d1, o, 4);
            }
            if (t4 == 0) {
                if (ALH == 1) {
                    if (gm0 < M) { atomicAdd(&als[gm0], s0); atomicAdd(&ald[gm0], d0); }
                    if (gm1 < M) { atomicAdd(&als[gm1], s1); atomicAdd(&ald[gm1], d1); }
                } else {
                    int head = (n0 + wn) >> 6;
                    if (gm0 < M) { atomicAdd(&als[gm0 * 4 + head], s0); atomicAdd(&ald[gm0 * 4 + head], d0); }
                    if (gm1 < M) { atomicAdd(&als[gm1 * 4 + head], s1); atomicAdd(&ald[gm1 * 4 + head], d1); }
                }
            }
        }
    }
}

// ---------------- edge bucketing by dst (counting sort; built once, reused) ------
__global__ void hist_k(const int* __restrict__ ei, int E, int N, int* __restrict__ cnt) {
    int e = blockIdx.x * 256 + threadIdx.x;
    if (e >= E + N) return;
    int d = (e < E) ? ei[E + e] : (e - E);
    atomicAdd(&cnt[d], 1);
}

#define SCAN_T 1024
__global__ __launch_bounds__(SCAN_T) void scan_k(const int* __restrict__ cnt,
                                                 int* __restrict__ rowst, int N, int Etot) {
    __shared__ int part[SCAN_T];
    int t = threadIdx.x;
    int ch = (N + SCAN_T - 1) / SCAN_T;
    int s = 0;
    for (int k = 0; k < ch; k++) {
        int idx = t * ch + k;
        if (idx < N) s += cnt[idx];
    }
    part[t] = s;
    __syncthreads();
    for (int off = 1; off < SCAN_T; off <<= 1) {
        int v = (t >= off) ? part[t - off] : 0;
        __syncthreads();
        part[t] += v;
        __syncthreads();
    }
    int run = (t > 0) ? part[t - 1] : 0;
    for (int k = 0; k < ch; k++) {
        int idx = t * ch + k;
        if (idx < N) { rowst[idx] = run; run += cnt[idx]; }
    }
    if (t == SCAN_T - 1) rowst[N] = Etot;
}

__global__ void permute_k(const int* __restrict__ ei, int E, int N,
                          int* __restrict__ cursor, int* __restrict__ src_sorted) {
    int e = blockIdx.x * 256 + threadIdx.x;
    if (e >= E + N) return;
    int s, d;
    if (e < E) { s = ei[e]; d = ei[E + e]; } else { s = d = e - E; }
    int pos = atomicAdd(&cursor[d], 1);
    src_sorted[pos] = s;
}

__device__ __forceinline__ float lrelu(float v) { return v > 0.f ? v : 0.2f * v; }

// ---------------- fused GAT aggregation + BN stats, warp per dst node, H=4 -------
__global__ __launch_bounds__(256) void gat_agg1_k(
        const int* __restrict__ rowst, const int* __restrict__ src_sorted,
        const float* __restrict__ h, const float* __restrict__ als,
        const float* __restrict__ ald, float* __restrict__ out, int N,
        float* __restrict__ bnS, float* __restrict__ bnQ) {
    __shared__ float wsum[8][DFEAT];
    __shared__ float wsq[8][DFEAT];
    __shared__ float4 spe[8][32];
    int t    = threadIdx.x;
    int wid  = t >> 5;
    int lane = t & 31;
    int w    = blockIdx.x * 8 + wid;
    bool act = w < N;
    int c0   = lane * 8;

    float o_[8];
#pragma unroll
    for (int k = 0; k < 8; k++) o_[k] = 0.f;

    if (act) {
        int start = rowst[w], end = rowst[w + 1];
        float4 aldv = *(const float4*)&ald[w * 4];
        int head = lane >> 3;
        float den0 = 0.f, den1 = 0.f, den2 = 0.f, den3 = 0.f;
        const float* speW = (const float*)&spe[wid][0];
#pragma unroll 1
        for (int base = start; base < end; base += 32) {
            int e = base + lane;
            int s = 0;
            float4 pe = make_float4(0.f, 0.f, 0.f, 0.f);
            if (e < end) {
                s = src_sorted[e];
                float4 av = *(const float4*)&als[s * 4];
                pe.x = __expf(lrelu(av.x + aldv.x));
                pe.y = __expf(lrelu(av.y + aldv.y));
                pe.z = __expf(lrelu(av.z + aldv.z));
                pe.w = __expf(lrelu(av.w + aldv.w));
                den0 += pe.x; den1 += pe.y; den2 += pe.z; den3 += pe.w;
            }
            spe[wid][lane] = pe;
            __syncwarp();
            int cnt = min(32, end - base);
            int j = 0;
#pragma unroll 1
            for (; j + 4 <= cnt; j += 4) {
                int sj0 = __shfl_sync(0xffffffffu, s, j + 0);
                int sj1 = __shfl_sync(0xffffffffu, s, j + 1);
                int sj2 = __shfl_sync(0xffffffffu, s, j + 2);
                int sj3 = __shfl_sync(0xffffffffu, s, j + 3);
                float p0 = speW[(j + 0) * 4 + head];
                float p1 = speW[(j + 1) * 4 + head];
                float p2 = speW[(j + 2) * 4 + head];
                float p3 = speW[(j + 3) * 4 + head];
                const float4* h0 = (const float4*)(h + (size_t)sj0 * DFEAT + c0);
                const float4* h1 = (const float4*)(h + (size_t)sj1 * DFEAT + c0);
                const float4* h2 = (const float4*)(h + (size_t)sj2 * DFEAT + c0);
                const float4* h3 = (const float4*)(h + (size_t)sj3 * DFEAT + c0);
                float4 a0 = h0[0], b0 = h0[1];
                float4 a1 = h1[0], b1 = h1[1];
                float4 a2 = h2[0], b2 = h2[1];
                float4 a3 = h3[0], b3 = h3[1];
                o_[0] += a0.x*p0 + a1.x*p1 + a2.x*p2 + a3.x*p3;
                o_[1] += a0.y*p0 + a1.y*p1 + a2.y*p2 + a3.y*p3;
                o_[2] += a0.z*p0 + a1.z*p1 + a2.z*p2 + a3.z*p3;
                o_[3] += a0.w*p0 + a1.w*p1 + a2.w*p2 + a3.w*p3;
                o_[4] += b0.x*p0 + b1.x*p1 + b2.x*p2 + b3.x*p3;
                o_[5] += b0.y*p0 + b1.y*p1 + b2.y*p2 + b3.y*p3;
                o_[6] += b0.z*p0 + b1.z*p1 + b2.z*p2 + b3.z*p3;
                o_[7] += b0.w*p0 + b1.w*p1 + b2.w*p2 + b3.w*p3;
            }
#pragma unroll 1
            for (; j < cnt; j++) {
                int sj = __shfl_sync(0xffffffffu, s, j);
                float pj = speW[j * 4 + head];
                const float4* hp = (const float4*)(h + (size_t)sj * DFEAT + c0);
                float4 v0 = hp[0], v1 = hp[1];
                o_[0] += v0.x * pj; o_[1] += v0.y * pj;
                o_[2] += v0.z * pj; o_[3] += v0.w * pj;
                o_[4] += v1.x * pj; o_[5] += v1.y * pj;
                o_[6] += v1.z * pj; o_[7] += v1.w * pj;
            }
            __syncwarp();
        }
#pragma unroll
        for (int o = 16; o; o >>= 1) {
            den0 += __shfl_xor_sync(0xffffffffu, den0, o);
            den1 += __shfl_xor_sync(0xffffffffu, den1, o);
            den2 += __shfl_xor_sync(0xffffffffu, den2, o);
            den3 += __shfl_xor_sync(0xffffffffu, den3, o);
        }
        float den = (head < 2) ? (head == 0 ? den0 : den1) : (head == 2 ? den2 : den3);
        float inv = 1.f / (den + 1e-16f);
#pragma unroll
        for (int k = 0; k < 8; k++) o_[k] *= inv;
        float* ob = out + (size_t)w * DFEAT + c0;
        *(float4*)ob       = make_float4(o_[0], o_[1], o_[2], o_[3]);
        *(float4*)(ob + 4) = make_float4(o_[4], o_[5], o_[6], o_[7]);
    }
#pragma unroll
    for (int k = 0; k < 8; k++) {
        wsum[wid][c0 + k] = o_[k];
        wsq[wid][c0 + k]  = o_[k] * o_[k];
    }
    __syncthreads();
    float s = 0.f, q = 0.f;
#pragma unroll
    for (int i = 0; i < 8; i++) { s += wsum[i][t]; q += wsq[i][t]; }
    atomicAdd(&bnS[t], s);
    atomicAdd(&bnQ[t], q);
}

// ---------------- fused GAT aggregation + BN stats, warp per dst node, H=1 -------
__global__ __launch_bounds__(256) void gat_agg2_k(
        const int* __restrict__ rowst, const int* __restrict__ src_sorted,
        const float* __restrict__ h, const float* __restrict__ als,
        const float* __restrict__ ald, float* __restrict__ out, int N,
        float* __restrict__ bnS, float* __restrict__ bnQ) {
    __shared__ float wsum[8][DFEAT];
    __shared__ float wsq[8][DFEAT];
    int t    = threadIdx.x;
    int wid  = t >> 5;
    int lane = t & 31;
    int w    = blockIdx.x * 8 + wid;
    bool act = w < N;
    int c0   = lane * 8;

    float o_[8];
#pragma unroll
    for (int k = 0; k < 8; k++) o_[k] = 0.f;

    if (act) {
        int start = rowst[w], end = rowst[w + 1];
        float aldd = ald[w];
        float den = 0.f;
#pragma unroll 1
        for (int base = start; base < end; base += 32) {
            int e = base + lane;
            int s = 0;
            float pe = 0.f;
            if (e < end) {
                s = src_sorted[e];
                pe = __expf(lrelu(als[s] + aldd));
                den += pe;
            }
            int cnt = min(32, end - base);
            int j = 0;
#pragma unroll 1
            for (; j + 4 <= cnt; j += 4) {
                int sj0 = __shfl_sync(0xffffffffu, s, j + 0);
                int sj1 = __shfl_sync(0xffffffffu, s, j + 1);
                int sj2 = __shfl_sync(0xffffffffu, s, j + 2);
                int sj3 = __shfl_sync(0xffffffffu, s, j + 3);
                float p0 = __shfl_sync(0xffffffffu, pe, j + 0);
                float p1 = __shfl_sync(0xffffffffu, pe, j + 1);
                float p2 = __shfl_sync(0xffffffffu, pe, j + 2);
                float p3 = __shfl_sync(0xffffffffu, pe, j + 3);
                const float4* h0 = (const float4*)(h + (size_t)sj0 * DFEAT + c0);
                const float4* h1 = (const float4*)(h + (size_t)sj1 * DFEAT + c0);
                const float4* h2 = (const float4*)(h + (size_t)sj2 * DFEAT + c0);
                const float4* h3 = (const float4*)(h + (size_t)sj3 * DFEAT + c0);
                float4 a0 = h0[0], b0 = h0[1];
                float4 a1 = h1[0], b1 = h1[1];
                float4 a2 = h2[0], b2 = h2[1];
                float4 a3 = h3[0], b3 = h3[1];
                o_[0] += a0.x*p0 + a1.x*p1 + a2.x*p2 + a3.x*p3;
                o_[1] += a0.y*p0 + a1.y*p1 + a2.y*p2 + a3.y*p3;
                o_[2] += a0.z*p0 + a1.z*p1 + a2.z*p2 + a3.z*p3;
                o_[3] += a0.w*p0 + a1.w*p1 + a2.w*p2 + a3.w*p3;
                o_[4] += b0.x*p0 + b1.x*p1 + b2.x*p2 + b3.x*p3;
                o_[5] += b0.y*p0 + b1.y*p1 + b2.y*p2 + b3.y*p3;
                o_[6] += b0.z*p0 + b1.z*p1 + b2.z*p2 + b3.z*p3;
                o_[7] += b0.w*p0 + b1.w*p1 + b2.w*p2 + b3.w*p3;
            }
#pragma unroll 1
            for (; j < cnt; j++) {
                int sj = __shfl_sync(0xffffffffu, s, j);
                float pj = __shfl_sync(0xffffffffu, pe, j);
                const float4* hp = (const float4*)(h + (size_t)sj * DFEAT + c0);
                float4 v0 = hp[0], v1 = hp[1];
                o_[0] += v0.x * pj; o_[1] += v0.y * pj;
                o_[2] += v0.z * pj; o_[3] += v0.w * pj;
                o_[4] += v1.x * pj; o_[5] += v1.y * pj;
                o_[6] += v1.z * pj; o_[7] += v1.w * pj;
            }
        }
#pragma unroll
        for (int o = 16; o; o >>= 1) den += __shfl_xor_sync(0xffffffffu, den, o);
        float inv = 1.f / (den + 1e-16f);
#pragma unroll
        for (int k = 0; k < 8; k++) o_[k] *= inv;
        float* ob = out + (size_t)w * DFEAT + c0;
        *(float4*)ob       = make_float4(o_[0], o_[1], o_[2], o_[3]);
        *(float4*)(ob + 4) = make_float4(o_[4], o_[5], o_[6], o_[7]);
    }
#pragma unroll
    for (int k = 0; k < 8; k++) {
        wsum[wid][c0 + k] = o_[k];
        wsq[wid][c0 + k]  = o_[k] * o_[k];
    }
    __syncthreads();
    float s = 0.f, q = 0.f;
#pragma unroll
    for (int i = 0; i < 8; i++) { s += wsum[i][t]; q += wsq[i][t]; }
    atomicAdd(&bnS[t], s);
    atomicAdd(&bnQ[t], q);
}

// ---------------- BN coefficient prep ----------------
__global__ void bnprep_k(const float* __restrict__ sum, const float* __restrict__ sumsq,
                         const float* __restrict__ g, const float* __restrict__ be,
                         float* __restrict__ sc, float* __restrict__ sh, int N) {
    int c = threadIdx.x;
    float invN = 1.f / (float)N;
    float m = sum[c] * invN;
    float v = sumsq[c] * invN - m * m;
    float s = g[c] * rsqrtf(v + 1e-5f);
    sc[c] = s;
    sh[c] = be[c] - m * s;
}

// ---- fused BN2-apply + relu + nodescore dot + pool accumulation (8 nodes/blk) ---
__global__ __launch_bounds__(256) void bn2_node_pool_k(
        float* __restrict__ x, const float* __restrict__ sc, const float* __restrict__ sh,
        const float* __restrict__ Wnode, const int* __restrict__ batch,
        float* __restrict__ poolS, float* __restrict__ out, int N) {
    __shared__ float spool[DFEAT];
    int t    = threadIdx.x;
    int wid  = t >> 5;
    int lane = t & 31;
    int n    = blockIdx.x * 8 + wid;
    int c0   = lane * 8;
    bool act = n < N;
    int gb0  = batch[min(blockIdx.x * 8, N - 1)];

    spool[t] = 0.f;
    __syncthreads();

    if (act) {
        float* xp = x + (size_t)n * DFEAT + c0;
        float4 v0 = *(float4*)xp, v1 = *(float4*)(xp + 4);
        float4 s0 = *(const float4*)&sc[c0], s1 = *(const float4*)&sc[c0 + 4];
        float4 h0 = *(const float4*)&sh[c0], h1 = *(const float4*)&sh[c0 + 4];
        float y[8];
        y[0] = fmaxf(v0.x * s0.x + h0.x, 0.f); y[1] = fmaxf(v0.y * s0.y + h0.y, 0.f);
        y[2] = fmaxf(v0.z * s0.z + h0.z, 0.f); y[3] = fmaxf(v0.w * s0.w + h0.w, 0.f);
        y[4] = fmaxf(v1.x * s1.x + h1.x, 0.f); y[5] = fmaxf(v1.y * s1.y + h1.y, 0.f);
        y[6] = fmaxf(v1.z * s1.z + h1.z, 0.f); y[7] = fmaxf(v1.w * s1.w + h1.w, 0.f);
        *(float4*)xp       = make_float4(y[0], y[1], y[2], y[3]);
        *(float4*)(xp + 4) = make_float4(y[4], y[5], y[6], y[7]);
        float4 w0 = *(const float4*)&Wnode[c0], w1 = *(const float4*)&Wnode[c0 + 4];
        float dot = y[0]*w0.x + y[1]*w0.y + y[2]*w0.z + y[3]*w0.w
                  + y[4]*w1.x + y[5]*w1.y + y[6]*w1.z + y[7]*w1.w;
#pragma unroll
        for (int o = 16; o; o >>= 1) dot += __shfl_down_sync(0xffffffffu, dot, o);
        if (!lane) out[n] = dot;   // raw; s2 + bias in fixup
        int g = batch[n];
        if (g == gb0) {
#pragma unroll
            for (int k = 0; k < 8; k++) atomicAdd(&spool[c0 + k], y[k]);
        } else {
#pragma unroll
            for (int k = 0; k < 8; k++) atomicAdd(&poolS[g * DFEAT + c0 + k], y[k]);
        }
    }
    __syncthreads();
    float pv = spool[t];
    if (pv != 0.f) atomicAdd(&poolS[gb0 * DFEAT + t], pv);
}

// ---------------- heads: block per graph; counts via binary search ---------------
__global__ __launch_bounds__(256) void heads_k(
        const float* __restrict__ xn, const int* __restrict__ target,
        const float* __restrict__ Wsh, const float* __restrict__ bsh,
        const float* __restrict__ Wnode,
        const float* __restrict__ Wtype, const float* __restrict__ btype,
        const float* __restrict__ Wcrit, const float* __restrict__ bcrit,
        const float* __restrict__ pool_sums, const int* __restrict__ batch,
        float* __restrict__ s2, float* __restrict__ out, int N) {
    __shared__ float gf[DFEAT];
    __shared__ float shm[DFEAT];
    __shared__ float part[8][6];
    __shared__ float cnt_sh;
    int b = blockIdx.x;
    int t = threadIdx.x;
    if (t == 0) {
        int lo = 0, hi = N;
        while (lo < hi) { int mid = (lo + hi) >> 1; if (batch[mid] < b) lo = mid + 1; else hi = mid; }
        int L = lo;
        lo = 0; hi = N;
        while (lo < hi) { int mid = (lo + hi) >> 1; if (batch[mid] < b + 1) lo = mid + 1; else hi = mid; }
        cnt_sh = (float)(lo - L);
    }
    __syncthreads();
    gf[t] = pool_sums[b * DFEAT + t] / fmaxf(cnt_sh, 1.f);
    __syncthreads();
    float acc = bsh[t];
    for (int k = 0; k < DFEAT; k++) acc += gf[k] * Wsh[k * DFEAT + t];
    shm[t] = fmaxf(acc, 0.f);
    __syncthreads();

    int tn = target[b];
    float xv = xn[(size_t)tn * DFEAT + t];
    float v[6];
    v[0] = shm[t] * Wnode[256 + t];
    v[1] = shm[t] * Wcrit[t];
#pragma unroll
    for (int a = 0; a < 4; a++)
        v[2 + a] = shm[t] * Wtype[t * 4 + a] + xv * Wtype[(256 + t) * 4 + a];
#pragma unroll
    for (int o = 16; o; o >>= 1)
#pragma unroll
        for (int i = 0; i < 6; i++) v[i] += __shfl_down_sync(0xffffffffu, v[i], o);
    if ((t & 31) == 0)
#pragma unroll
        for (int i = 0; i < 6; i++) part[t >> 5][i] = v[i];
    __syncthreads();
    if (t == 0) {
        float r[6] = {0.f, 0.f, 0.f, 0.f, 0.f, 0.f};
        for (int w = 0; w < 8; w++)
#pragma unroll
            for (int i = 0; i < 6; i++) r[i] += part[w][i];
        s2[b] = r[0];
        out[N + 32 + b] = r[1] + bcrit[0];
#pragma unroll
        for (int a = 0; a < 4; a++) out[N + b * 4 + a] = r[2 + a] + btype[a];
    }
}

// ---------------- fixup: add s2[batch] + bnode to node scores ----------------
__global__ void fixup_k(float* __restrict__ out, const int* __restrict__ batch,
                        const float* __restrict__ s2, const float* __restrict__ bnode, int N) {
    int i = blockIdx.x * 256 + threadIdx.x;
    if (i < N) out[i] += s2[batch[i]] + bnode[0];
}

// ---------------- host orchestration ----------------
extern "C" void kernel_launch(void* const* d_in, const int* in_sizes, int n_in,
                              void* d_out, int out_size) {
    const float* x      = (const float*)d_in[0];
    const int*   ei     = (const int*)d_in[1];
    const int*   batch  = (const int*)d_in[2];
    const int*   target = (const int*)d_in[3];
    const float* W1     = (const float*)d_in[4];
    const float* a1s    = (const float*)d_in[5];
    const float* a1d    = (const float*)d_in[6];
    const float* W2     = (const float*)d_in[8];
    const float* a2s    = (const float*)d_in[9];
    const float* a2d    = (const float*)d_in[10];
    const float* g1     = (const float*)d_in[12];
    const float* be1    = (const float*)d_in[13];
    const float* g2     = (const float*)d_in[14];
    const float* be2    = (const float*)d_in[15];
    const float* Wsh    = (const float*)d_in[16];
    const float* bsh    = (const float*)d_in[17];
    const float* Wnode  = (const float*)d_in[18];
    const float* bnode  = (const float*)d_in[19];
    const float* Wtype  = (const float*)d_in[20];
    const float* btype  = (const float*)d_in[21];
    const float* Wcrit  = (const float*)d_in[22];
    const float* bcrit  = (const float*)d_in[23];
    float* out = (float*)d_out;

    int N = in_sizes[2];
    int F = in_sizes[0] / N;
    int E = in_sizes[1] / 2;
    int Etot = E + N;

    float *bufA, *bufB, *als1, *ald1, *als2, *ald2;
    float *bnS, *bnQ, *sc1, *sh1, *sc2, *sh2, *poolS, *s2;
    int *cnt, *rowst, *cursor, *src_sorted;
    cudaGetSymbolAddress((void**)&bufA,  g_bufA);
    cudaGetSymbolAddress((void**)&bufB,  g_bufB);
    cudaGetSymbolAddress((void**)&als1,  g_als1);
    cudaGetSymbolAddress((void**)&ald1,  g_ald1);
    cudaGetSymbolAddress((void**)&als2,  g_als2);
    cudaGetSymbolAddress((void**)&ald2,  g_ald2);
    cudaGetSymbolAddress((void**)&cnt,   g_cnt);
    cudaGetSymbolAddress((void**)&rowst, g_rowst);
    cudaGetSymbolAddress((void**)&cursor, g_cursor);
    cudaGetSymbolAddress((void**)&src_sorted, g_src_sorted);
    cudaGetSymbolAddress((void**)&bnS,   g_bn_sum);
    cudaGetSymbolAddress((void**)&bnQ,   g_bn_sumsq);
    cudaGetSymbolAddress((void**)&sc1,   g_sc1);
    cudaGetSymbolAddress((void**)&sh1,   g_sh1);
    cudaGetSymbolAddress((void**)&sc2,   g_sc2);
    cudaGetSymbolAddress((void**)&sh2,   g_sh2);
    cudaGetSymbolAddress((void**)&poolS, g_pool_sum);
    cudaGetSymbolAddress((void**)&s2,    g_s2);

    // ---- zero init (async memsets; graph-capturable) ----
    cudaMemsetAsync(cnt,   0, (size_t)(N + 1) * sizeof(int));
    cudaMemsetAsync(als1,  0, (size_t)N * H1HEADS * sizeof(float));
    cudaMemsetAsync(ald1,  0, (size_t)N * H1HEADS * sizeof(float));
    cudaMemsetAsync(als2,  0, (size_t)N * sizeof(float));
    cudaMemsetAsync(ald2,  0, (size_t)N * sizeof(float));
    cudaMemsetAsync(poolS, 0, NGRAPHS * DFEAT * sizeof(float));
    cudaMemsetAsync(bnS,   0, DFEAT * sizeof(float));
    cudaMemsetAsync(bnQ,   0, DFEAT * sizeof(float));

    // ---- edge bucketing (shared by both layers) ----
    hist_k<<<cdiv(Etot, 256), 256>>>(ei, E, N, cnt);
    scan_k<<<1, SCAN_T>>>(cnt, rowst, N, Etot);
    cudaMemcpyAsync(cursor, rowst, (size_t)N * sizeof(int), cudaMemcpyDeviceToDevice);
    permute_k<<<cdiv(Etot, 256), 256>>>(ei, E, N, cursor, src_sorted);

    // ---- GAT layer 1: tf32 MMA GEMM(4-head al1 epilogue) -> agg(+BN1 stats) ----
    {
        dim3 grid(DFEAT / 128, cdiv(N, 128));
        mma_gemm_k<false, 4><<<grid, 256>>>(x, W1, bufA, N, F, DFEAT,
                                            nullptr, nullptr, a1s, a1d, als1, ald1);
    }
    gat_agg1_k<<<cdiv(N, 8), 256>>>(rowst, src_sorted, bufA, als1, ald1, bufB, N, bnS, bnQ);
    bnprep_k<<<1, 256>>>(bnS, bnQ, g1, be1, sc1, sh1, N);

    // ---- GAT layer 2: tf32 MMA GEMM(BN1 on A, +al2) -> agg(+BN2 stats) ----
    {
        dim3 grid(DFEAT / 128, cdiv(N, 128));
        mma_gemm_k<true, 1><<<grid, 256>>>(bufB, W2, bufA, N, DFEAT, DFEAT,
                                           sc1, sh1, a2s, a2d, als2, ald2);
    }
    cudaMemsetAsync(bnS, 0, DFEAT * sizeof(float));
    cudaMemsetAsync(bnQ, 0, DFEAT * sizeof(float));
    gat_agg2_k<<<cdiv(N, 8), 256>>>(rowst, src_sorted, bufA, als2, ald2, bufB, N, bnS, bnQ);
    bnprep_k<<<1, 256>>>(bnS, bnQ, g2, be2, sc2, sh2, N);

    // ---- BN2 apply + nodescore dot + pool accumulation ----
    bn2_node_pool_k<<<cdiv(N, 8), 256>>>(bufB, sc2, sh2, Wnode, batch, poolS, out, N);

    // ---- heads + fixup ----
    heads_k<<<NGRAPHS, 256>>>(bufB, target, Wsh, bsh, Wnode, Wtype, btype, Wcrit, bcrit,
                              poolS, batch, s2, out, N);
    fixup_k<<<cdiv(N, 256), 256>>>(out, batch, s2, bnode, N);
}

// round 17
// speedup vs baseline: 1.4401x; 1.4401x over previous
#include <cuda_runtime.h>
#include <cstdint>

// Problem constants (fixed shapes for this dataset)
#define NNODES   50000
#define DFEAT    256
#define H1HEADS  4
#define NGRAPHS  8
#define EMAX     400000
#define ETOTMAX  (EMAX + NNODES)

// ---------------- scratch (static device globals; no allocation) ----------------
__device__ float g_bufA[NNODES * DFEAT];   // linear-layer output (h1 / h2)
__device__ float g_bufB[NNODES * DFEAT];   // aggregation output
__device__ float g_als1[NNODES * H1HEADS];
__device__ float g_ald1[NNODES * H1HEADS];
__device__ float g_als2[NNODES];
__device__ float g_ald2[NNODES];
__device__ int   g_cnt[NNODES + 1];
__device__ int   g_rowst[NNODES + 1];
__device__ int   g_cursor[NNODES];
__device__ int   g_src_sorted[ETOTMAX];
__device__ float g_bn_sum[DFEAT];
__device__ float g_bn_sumsq[DFEAT];
__device__ float g_sc1[DFEAT];
__device__ float g_sh1[DFEAT];
__device__ float g_sc2[DFEAT];
__device__ float g_sh2[DFEAT];
__device__ float g_pool_sum[NGRAPHS * DFEAT];
__device__ float g_s2[NGRAPHS];

static inline int cdiv(int a, int b) { return (a + b - 1) / b; }

// ---------------- tf32 helpers ----------------
__device__ __forceinline__ uint32_t f2tf32(float x) {
    uint32_t u;
    asm("cvt.rna.tf32.f32 %0, %1;" : "=r"(u) : "f"(x));
    return u;
}

__device__ __forceinline__ void mma_tf32(float* d, const uint32_t* a, const uint32_t* b) {
    asm volatile(
        "mma.sync.aligned.m16n8k8.row.col.f32.tf32.tf32.f32 "
        "{%0,%1,%2,%3}, {%4,%5,%6,%7}, {%8,%9}, {%0,%1,%2,%3};"
        : "+f"(d[0]), "+f"(d[1]), "+f"(d[2]), "+f"(d[3])
        : "r"(a[0]), "r"(a[1]), "r"(a[2]), "r"(a[3]), "r"(b[0]), "r"(b[1]));
}

// ---------------- tf32 MMA GEMM: 128x128 block, warps 4x2 (each 32x64) ----------
#define MTK 16
template <bool BNA, bool ALH1>
__global__ __launch_bounds__(256) void mma_gemm_k(
        const float* __restrict__ A, const float* __restrict__ B,
        float* __restrict__ C, int M, int K, int Nn,
        const float* __restrict__ sc, const float* __restrict__ sh,
        const float* __restrict__ asrc, const float* __restrict__ adst,
        float* __restrict__ als, float* __restrict__ ald) {
    __shared__ uint32_t As[MTK][128 + 8];
    __shared__ uint32_t Bs[MTK][128 + 8];
    int t    = threadIdx.x;
    int lane = t & 31;
    int wid  = t >> 5;
    int wm   = (wid >> 1) * 32;
    int wn   = (wid & 1) * 64;
    int m0   = blockIdx.y * 128;
    int n0   = blockIdx.x * 128;
    int g    = lane >> 2;
    int t4   = lane & 3;

    float acc[2][8][4];
#pragma unroll
    for (int mt = 0; mt < 2; mt++)
#pragma unroll
        for (int nt = 0; nt < 8; nt++)
#pragma unroll
            for (int i = 0; i < 4; i++) acc[mt][nt][i] = 0.f;

    for (int k0 = 0; k0 < K; k0 += MTK) {
#pragma unroll
        for (int i = 0; i < 2; i++) {
            int f  = t + i * 256;
            int r  = f >> 2;
            int c4 = (f & 3) * 4;
            int gm = m0 + r;
            float4 v = make_float4(0.f, 0.f, 0.f, 0.f);
            if (gm < M) v = *(const float4*)(A + (size_t)gm * K + k0 + c4);
            if (BNA) {
                v.x = fmaxf(v.x * sc[k0 + c4 + 0] + sh[k0 + c4 + 0], 0.f);
                v.y = fmaxf(v.y * sc[k0 + c4 + 1] + sh[k0 + c4 + 1], 0.f);
                v.z = fmaxf(v.z * sc[k0 + c4 + 2] + sh[k0 + c4 + 2], 0.f);
                v.w = fmaxf(v.w * sc[k0 + c4 + 3] + sh[k0 + c4 + 3], 0.f);
            }
            As[c4 + 0][r] = f2tf32(v.x); As[c4 + 1][r] = f2tf32(v.y);
            As[c4 + 2][r] = f2tf32(v.z); As[c4 + 3][r] = f2tf32(v.w);
        }
#pragma unroll
        for (int i = 0; i < 2; i++) {
            int f  = t + i * 256;
            int r  = f >> 5;
            int c4 = (f & 31) * 4;
            float4 v = *(const float4*)(B + (size_t)(k0 + r) * Nn + n0 + c4);
            Bs[r][c4 + 0] = f2tf32(v.x); Bs[r][c4 + 1] = f2tf32(v.y);
            Bs[r][c4 + 2] = f2tf32(v.z); Bs[r][c4 + 3] = f2tf32(v.w);
        }
        __syncthreads();
#pragma unroll
        for (int ks = 0; ks < MTK; ks += 8) {
            uint32_t af[2][4];
#pragma unroll
            for (int mt = 0; mt < 2; mt++) {
                int mr = wm + mt * 16;
                af[mt][0] = As[ks + t4][mr + g];
                af[mt][1] = As[ks + t4][mr + g + 8];
                af[mt][2] = As[ks + t4 + 4][mr + g];
                af[mt][3] = As[ks + t4 + 4][mr + g + 8];
            }
            uint32_t bf[8][2];
#pragma unroll
            for (int nt = 0; nt < 8; nt++) {
                int nc = wn + nt * 8 + g;
                bf[nt][0] = Bs[ks + t4][nc];
                bf[nt][1] = Bs[ks + t4 + 4][nc];
            }
#pragma unroll
            for (int mt = 0; mt < 2; mt++)
#pragma unroll
                for (int nt = 0; nt < 8; nt++)
                    mma_tf32(acc[mt][nt], af[mt], bf[nt]);
        }
        __syncthreads();
    }

#pragma unroll
    for (int mt = 0; mt < 2; mt++) {
        int gm0 = m0 + wm + mt * 16 + g;
        int gm1 = gm0 + 8;
        float s0 = 0.f, d0 = 0.f, s1 = 0.f, d1 = 0.f;
#pragma unroll
        for (int nt = 0; nt < 8; nt++) {
            int cb = n0 + wn + nt * 8 + 2 * t4;
            if (gm0 < M)
                *(float2*)(C + (size_t)gm0 * Nn + cb) = make_float2(acc[mt][nt][0], acc[mt][nt][1]);
            if (gm1 < M)
                *(float2*)(C + (size_t)gm1 * Nn + cb) = make_float2(acc[mt][nt][2], acc[mt][nt][3]);
            if (ALH1) {
                float w0s = asrc[cb], w1s = asrc[cb + 1];
                float w0d = adst[cb], w1d = adst[cb + 1];
                s0 += acc[mt][nt][0] * w0s + acc[mt][nt][1] * w1s;
                d0 += acc[mt][nt][0] * w0d + acc[mt][nt][1] * w1d;
                s1 += acc[mt][nt][2] * w0s + acc[mt][nt][3] * w1s;
                d1 += acc[mt][nt][2] * w0d + acc[mt][nt][3] * w1d;
            }
        }
        if (ALH1) {
#pragma unroll
            for (int o = 2; o; o >>= 1) {
                s0 += __shfl_down_sync(0xffffffffu, s0, o, 4);
                d0 += __shfl_down_sync(0xffffffffu, d0, o, 4);
                s1 += __shfl_down_sync(0xffffffffu, s1, o, 4);
                d1 += __shfl_down_sync(0xffffffffu, d1, o, 4);
            }
            if (t4 == 0) {
                if (gm0 < M) { atomicAdd(&als[gm0], s0); atomicAdd(&ald[gm0], d0); }
                if (gm1 < M) { atomicAdd(&als[gm1], s1); atomicAdd(&ald[gm1], d1); }
            }
        }
    }
}

// ---------------- FFMA SGEMM 128x64 (GEMM1, K=64) + al1 epilogue ----------------
#define TM 128
#define TK 16
__global__ __launch_bounds__(256) void sgemm1_k(
        const float* __restrict__ A, const float* __restrict__ B,
        float* __restrict__ C, int M, int K, int Nn,
        const float* __restrict__ asrc, const float* __restrict__ adst,
        float* __restrict__ als, float* __restrict__ ald) {
    constexpr int NR = 4;
    constexpr int TNB = 16 * NR;
    __shared__ float As[TK][TM + 4];
    __shared__ float Bs[TK][TNB];
    int t  = threadIdx.x;
    int m0 = blockIdx.y * TM;
    int n0 = blockIdx.x * TNB;
    int tx = t & 15;
    int ty = t >> 4;
    float acc[8][NR];
#pragma unroll
    for (int i = 0; i < 8; i++)
#pragma unroll
        for (int j = 0; j < NR; j++) acc[i][j] = 0.f;

    for (int k0 = 0; k0 < K; k0 += TK) {
#pragma unroll
        for (int i = 0; i < 2; i++) {
            int f  = t + i * 256;
            int r  = f >> 2;
            int c4 = (f & 3) * 4;
            int gm = m0 + r;
            float4 v = make_float4(0.f, 0.f, 0.f, 0.f);
            if (gm < M) v = *(const float4*)(A + (size_t)gm * K + k0 + c4);
            As[c4 + 0][r] = v.x; As[c4 + 1][r] = v.y;
            As[c4 + 2][r] = v.z; As[c4 + 3][r] = v.w;
        }
        {
            int r  = t >> 4;
            int c4 = (t & 15) * 4;
            float4 v = *(const float4*)(B + (size_t)(k0 + r) * Nn + n0 + c4);
            *(float4*)&Bs[r][c4] = v;
        }
        __syncthreads();
#pragma unroll
        for (int k = 0; k < TK; k++) {
            float a_[8], b_[NR];
            *(float4*)(a_)     = *(float4*)&As[k][ty * 8];
            *(float4*)(a_ + 4) = *(float4*)&As[k][ty * 8 + 4];
            *(float4*)(b_)     = *(float4*)&Bs[k][tx * NR];
#pragma unroll
            for (int i = 0; i < 8; i++)
#pragma unroll
                for (int j = 0; j < NR; j++) acc[i][j] += a_[i] * b_[j];
        }
        __syncthreads();
    }

    float as_r[NR], ad_r[NR];
#pragma unroll
    for (int j = 0; j < NR; j++) {
        int col = n0 + tx * NR + j;
        as_r[j] = asrc[col];
        ad_r[j] = adst[col];
    }

#pragma unroll
    for (int i = 0; i < 8; i++) {
        int gm = m0 + ty * 8 + i;
        if (gm < M) {
            float* cp = C + (size_t)gm * Nn + n0 + tx * NR;
            *(float4*)cp = make_float4(acc[i][0], acc[i][1], acc[i][2], acc[i][3]);
            float s = 0.f, d = 0.f;
#pragma unroll
            for (int j = 0; j < NR; j++) { s += acc[i][j] * as_r[j]; d += acc[i][j] * ad_r[j]; }
#pragma unroll
            for (int o = 8; o; o >>= 1) {
                s += __shfl_down_sync(0xffffffffu, s, o, 16);
                d += __shfl_down_sync(0xffffffffu, d, o, 16);
            }
            if (tx == 0) {
                int head = n0 >> 6;
                atomicAdd(&als[gm * 4 + head], s);
                atomicAdd(&ald[gm * 4 + head], d);
            }
        }
    }
}

// ---------------- edge bucketing by dst (counting sort; built once, reused) ------
__global__ void hist_k(const int* __restrict__ ei, int E, int N, int* __restrict__ cnt) {
    int e = blockIdx.x * 256 + threadIdx.x;
    if (e >= E + N) return;
    int d = (e < E) ? ei[E + e] : (e - E);
    atomicAdd(&cnt[d], 1);
}

#define SCAN_T 1024
__global__ __launch_bounds__(SCAN_T) void scan_k(const int* __restrict__ cnt,
                                                 int* __restrict__ rowst, int N, int Etot) {
    __shared__ int part[SCAN_T];
    int t = threadIdx.x;
    int ch = (N + SCAN_T - 1) / SCAN_T;
    int s = 0;
    for (int k = 0; k < ch; k++) {
        int idx = t * ch + k;
        if (idx < N) s += cnt[idx];
    }
    part[t] = s;
    __syncthreads();
    for (int off = 1; off < SCAN_T; off <<= 1) {
        int v = (t >= off) ? part[t - off] : 0;
        __syncthreads();
        part[t] += v;
        __syncthreads();
    }
    int run = (t > 0) ? part[t - 1] : 0;
    for (int k = 0; k < ch; k++) {
        int idx = t * ch + k;
        if (idx < N) { rowst[idx] = run; run += cnt[idx]; }
    }
    if (t == SCAN_T - 1) rowst[N] = Etot;
}

__global__ void permute_k(const int* __restrict__ ei, int E, int N,
                          int* __restrict__ cursor, int* __restrict__ src_sorted) {
    int e = blockIdx.x * 256 + threadIdx.x;
    if (e >= E + N) return;
    int s, d;
    if (e < E) { s = ei[e]; d = ei[E + e]; } else { s = d = e - E; }
    int pos = atomicAdd(&cursor[d], 1);
    src_sorted[pos] = s;
}

__device__ __forceinline__ float lrelu(float v) { return v > 0.f ? v : 0.2f * v; }

// ---------------- fused GAT aggregation + BN stats, warp per dst node, H=4 -------
__global__ __launch_bounds__(256) void gat_agg1_k(
        const int* __restrict__ rowst, const int* __restrict__ src_sorted,
        const float* __restrict__ h, const float* __restrict__ als,
        const float* __restrict__ ald, float* __restrict__ out, int N,
        float* __restrict__ bnS, float* __restrict__ bnQ) {
    __shared__ float wsum[8][DFEAT];
    __shared__ float wsq[8][DFEAT];
    __shared__ float4 spe[8][32];
    int t    = threadIdx.x;
    int wid  = t >> 5;
    int lane = t & 31;
    int w    = blockIdx.x * 8 + wid;
    bool act = w < N;
    int c0   = lane * 8;

    float o_[8];
#pragma unroll
    for (int k = 0; k < 8; k++) o_[k] = 0.f;

    if (act) {
        int start = rowst[w], end = rowst[w + 1];
        float4 aldv = *(const float4*)&ald[w * 4];
        int head = lane >> 3;
        float den0 = 0.f, den1 = 0.f, den2 = 0.f, den3 = 0.f;
        const float* speW = (const float*)&spe[wid][0];
#pragma unroll 1
        for (int base = start; base < end; base += 32) {
            int e = base + lane;
            int s = 0;
            float4 pe = make_float4(0.f, 0.f, 0.f, 0.f);
            if (e < end) {
                s = src_sorted[e];
                float4 av = *(const float4*)&als[s * 4];
                pe.x = __expf(lrelu(av.x + aldv.x));
                pe.y = __expf(lrelu(av.y + aldv.y));
                pe.z = __expf(lrelu(av.z + aldv.z));
                pe.w = __expf(lrelu(av.w + aldv.w));
                den0 += pe.x; den1 += pe.y; den2 += pe.z; den3 += pe.w;
            }
            spe[wid][lane] = pe;
            __syncwarp();
            int cnt = min(32, end - base);
            int j = 0;
#pragma unroll 1
            for (; j + 4 <= cnt; j += 4) {
                int sj0 = __shfl_sync(0xffffffffu, s, j + 0);
                int sj1 = __shfl_sync(0xffffffffu, s, j + 1);
                int sj2 = __shfl_sync(0xffffffffu, s, j + 2);
                int sj3 = __shfl_sync(0xffffffffu, s, j + 3);
                float p0 = speW[(j + 0) * 4 + head];
                float p1 = speW[(j + 1) * 4 + head];
                float p2 = speW[(j + 2) * 4 + head];
                float p3 = speW[(j + 3) * 4 + head];
                const float4* h0 = (const float4*)(h + (size_t)sj0 * DFEAT + c0);
                const float4* h1 = (const float4*)(h + (size_t)sj1 * DFEAT + c0);
                const float4* h2 = (const float4*)(h + (size_t)sj2 * DFEAT + c0);
                const float4* h3 = (const float4*)(h + (size_t)sj3 * DFEAT + c0);
                float4 a0 = h0[0], b0 = h0[1];
                float4 a1 = h1[0], b1 = h1[1];
                float4 a2 = h2[0], b2 = h2[1];
                float4 a3 = h3[0], b3 = h3[1];
                o_[0] += a0.x*p0 + a1.x*p1 + a2.x*p2 + a3.x*p3;
                o_[1] += a0.y*p0 + a1.y*p1 + a2.y*p2 + a3.y*p3;
                o_[2] += a0.z*p0 + a1.z*p1 + a2.z*p2 + a3.z*p3;
                o_[3] += a0.w*p0 + a1.w*p1 + a2.w*p2 + a3.w*p3;
                o_[4] += b0.x*p0 + b1.x*p1 + b2.x*p2 + b3.x*p3;
                o_[5] += b0.y*p0 + b1.y*p1 + b2.y*p2 + b3.y*p3;
                o_[6] += b0.z*p0 + b1.z*p1 + b2.z*p2 + b3.z*p3;
                o_[7] += b0.w*p0 + b1.w*p1 + b2.w*p2 + b3.w*p3;
            }
#pragma unroll 1
            for (; j < cnt; j++) {
                int sj = __shfl_sync(0xffffffffu, s, j);
                float pj = speW[j * 4 + head];
                const float4* hp = (const float4*)(h + (size_t)sj * DFEAT + c0);
                float4 v0 = hp[0], v1 = hp[1];
                o_[0] += v0.x * pj; o_[1] += v0.y * pj;
                o_[2] += v0.z * pj; o_[3] += v0.w * pj;
                o_[4] += v1.x * pj; o_[5] += v1.y * pj;
                o_[6] += v1.z * pj; o_[7] += v1.w * pj;
            }
            __syncwarp();
        }
#pragma unroll
        for (int o = 16; o; o >>= 1) {
            den0 += __shfl_xor_sync(0xffffffffu, den0, o);
            den1 += __shfl_xor_sync(0xffffffffu, den1, o);
            den2 += __shfl_xor_sync(0xffffffffu, den2, o);
            den3 += __shfl_xor_sync(0xffffffffu, den3, o);
        }
        float den = (head < 2) ? (head == 0 ? den0 : den1) : (head == 2 ? den2 : den3);
        float inv = 1.f / (den + 1e-16f);
#pragma unroll
        for (int k = 0; k < 8; k++) o_[k] *= inv;
        float* ob = out + (size_t)w * DFEAT + c0;
        *(float4*)ob       = make_float4(o_[0], o_[1], o_[2], o_[3]);
        *(float4*)(ob + 4) = make_float4(o_[4], o_[5], o_[6], o_[7]);
    }
#pragma unroll
    for (int k = 0; k < 8; k++) {
        wsum[wid][c0 + k] = o_[k];
        wsq[wid][c0 + k]  = o_[k] * o_[k];
    }
    __syncthreads();
    float s = 0.f, q = 0.f;
#pragma unroll
    for (int i = 0; i < 8; i++) { s += wsum[i][t]; q += wsq[i][t]; }
    atomicAdd(&bnS[t], s);
    atomicAdd(&bnQ[t], q);
}

// ---------------- fused GAT aggregation + BN stats, warp per dst node, H=1 -------
__global__ __launch_bounds__(256) void gat_agg2_k(
        const int* __restrict__ rowst, const int* __restrict__ src_sorted,
        const float* __restrict__ h, const float* __restrict__ als,
        const float* __restrict__ ald, float* __restrict__ out, int N,
        float* __restrict__ bnS, float* __restrict__ bnQ) {
    __shared__ float wsum[8][DFEAT];
    __shared__ float wsq[8][DFEAT];
    int t    = threadIdx.x;
    int wid  = t >> 5;
    int lane = t & 31;
    int w    = blockIdx.x * 8 + wid;
    bool act = w < N;
    int c0   = lane * 8;

    float o_[8];
#pragma unroll
    for (int k = 0; k < 8; k++) o_[k] = 0.f;

    if (act) {
        int start = rowst[w], end = rowst[w + 1];
        float aldd = ald[w];
        float den = 0.f;
#pragma unroll 1
        for (int base = start; base < end; base += 32) {
            int e = base + lane;
            int s = 0;
            float pe = 0.f;
            if (e < end) {
                s = src_sorted[e];
                pe = __expf(lrelu(als[s] + aldd));
                den += pe;
            }
            int cnt = min(32, end - base);
            int j = 0;
#pragma unroll 1
            for (; j + 4 <= cnt; j += 4) {
                int sj0 = __shfl_sync(0xffffffffu, s, j + 0);
                int sj1 = __shfl_sync(0xffffffffu, s, j + 1);
                int sj2 = __shfl_sync(0xffffffffu, s, j + 2);
                int sj3 = __shfl_sync(0xffffffffu, s, j + 3);
                float p0 = __shfl_sync(0xffffffffu, pe, j + 0);
                float p1 = __shfl_sync(0xffffffffu, pe, j + 1);
                float p2 = __shfl_sync(0xffffffffu, pe, j + 2);
                float p3 = __shfl_sync(0xffffffffu, pe, j + 3);
                const float4* h0 = (const float4*)(h + (size_t)sj0 * DFEAT + c0);
                const float4* h1 = (const float4*)(h + (size_t)sj1 * DFEAT + c0);
                const float4* h2 = (const float4*)(h + (size_t)sj2 * DFEAT + c0);
                const float4* h3 = (const float4*)(h + (size_t)sj3 * DFEAT + c0);
                float4 a0 = h0[0], b0 = h0[1];
                float4 a1 = h1[0], b1 = h1[1];
                float4 a2 = h2[0], b2 = h2[1];
                float4 a3 = h3[0], b3 = h3[1];
                o_[0] += a0.x*p0 + a1.x*p1 + a2.x*p2 + a3.x*p3;
                o_[1] += a0.y*p0 + a1.y*p1 + a2.y*p2 + a3.y*p3;
                o_[2] += a0.z*p0 + a1.z*p1 + a2.z*p2 + a3.z*p3;
                o_[3] += a0.w*p0 + a1.w*p1 + a2.w*p2 + a3.w*p3;
                o_[4] += b0.x*p0 + b1.x*p1 + b2.x*p2 + b3.x*p3;
                o_[5] += b0.y*p0 + b1.y*p1 + b2.y*p2 + b3.y*p3;
                o_[6] += b0.z*p0 + b1.z*p1 + b2.z*p2 + b3.z*p3;
                o_[7] += b0.w*p0 + b1.w*p1 + b2.w*p2 + b3.w*p3;
            }
#pragma unroll 1
            for (; j < cnt; j++) {
                int sj = __shfl_sync(0xffffffffu, s, j);
                float pj = __shfl_sync(0xffffffffu, pe, j);
                const float4* hp = (const float4*)(h + (size_t)sj * DFEAT + c0);
                float4 v0 = hp[0], v1 = hp[1];
                o_[0] += v0.x * pj; o_[1] += v0.y * pj;
                o_[2] += v0.z * pj; o_[3] += v0.w * pj;
                o_[4] += v1.x * pj; o_[5] += v1.y * pj;
                o_[6] += v1.z * pj; o_[7] += v1.w * pj;
            }
        }
#pragma unroll
        for (int o = 16; o; o >>= 1) den += __shfl_xor_sync(0xffffffffu, den, o);
        float inv = 1.f / (den + 1e-16f);
#pragma unroll
        for (int k = 0; k < 8; k++) o_[k] *= inv;
        float* ob = out + (size_t)w * DFEAT + c0;
        *(float4*)ob       = make_float4(o_[0], o_[1], o_[2], o_[3]);
        *(float4*)(ob + 4) = make_float4(o_[4], o_[5], o_[6], o_[7]);
    }
#pragma unroll
    for (int k = 0; k < 8; k++) {
        wsum[wid][c0 + k] = o_[k];
        wsq[wid][c0 + k]  = o_[k] * o_[k];
    }
    __syncthreads();
    float s = 0.f, q = 0.f;
#pragma unroll
    for (int i = 0; i < 8; i++) { s += wsum[i][t]; q += wsq[i][t]; }
    atomicAdd(&bnS[t], s);
    atomicAdd(&bnQ[t], q);
}

// ---------------- BN coefficient prep ----------------
__global__ void bnprep_k(const float* __restrict__ sum, const float* __restrict__ sumsq,
                         const float* __restrict__ g, const float* __restrict__ be,
                         float* __restrict__ sc, float* __restrict__ sh, int N) {
    int c = threadIdx.x;
    float invN = 1.f / (float)N;
    float m = sum[c] * invN;
    float v = sumsq[c] * invN - m * m;
    float s = g[c] * rsqrtf(v + 1e-5f);
    sc[c] = s;
    sh[c] = be[c] - m * s;
}

// ---- fused BN2-apply + relu + nodescore dot + pool accumulation (8 nodes/blk) ---
__global__ __launch_bounds__(256) void bn2_node_pool_k(
        float* __restrict__ x, const float* __restrict__ sc, const float* __restrict__ sh,
        const float* __restrict__ Wnode, const int* __restrict__ batch,
        float* __restrict__ poolS, float* __restrict__ out, int N) {
    __shared__ float spool[DFEAT];
    int t    = threadIdx.x;
    int wid  = t >> 5;
    int lane = t & 31;
    int n    = blockIdx.x * 8 + wid;
    int c0   = lane * 8;
    bool act = n < N;
    int gb0  = batch[min(blockIdx.x * 8, N - 1)];

    spool[t] = 0.f;
    __syncthreads();

    if (act) {
        float* xp = x + (size_t)n * DFEAT + c0;
        float4 v0 = *(float4*)xp, v1 = *(float4*)(xp + 4);
        float4 s0 = *(const float4*)&sc[c0], s1 = *(const float4*)&sc[c0 + 4];
        float4 h0 = *(const float4*)&sh[c0], h1 = *(const float4*)&sh[c0 + 4];
        float y[8];
        y[0] = fmaxf(v0.x * s0.x + h0.x, 0.f); y[1] = fmaxf(v0.y * s0.y + h0.y, 0.f);
        y[2] = fmaxf(v0.z * s0.z + h0.z, 0.f); y[3] = fmaxf(v0.w * s0.w + h0.w, 0.f);
        y[4] = fmaxf(v1.x * s1.x + h1.x, 0.f); y[5] = fmaxf(v1.y * s1.y + h1.y, 0.f);
        y[6] = fmaxf(v1.z * s1.z + h1.z, 0.f); y[7] = fmaxf(v1.w * s1.w + h1.w, 0.f);
        *(float4*)xp       = make_float4(y[0], y[1], y[2], y[3]);
        *(float4*)(xp + 4) = make_float4(y[4], y[5], y[6], y[7]);
        float4 w0 = *(const float4*)&Wnode[c0], w1 = *(const float4*)&Wnode[c0 + 4];
        float dot = y[0]*w0.x + y[1]*w0.y + y[2]*w0.z + y[3]*w0.w
                  + y[4]*w1.x + y[5]*w1.y + y[6]*w1.z + y[7]*w1.w;
#pragma unroll
        for (int o = 16; o; o >>= 1) dot += __shfl_down_sync(0xffffffffu, dot, o);
        if (!lane) out[n] = dot;   // raw; s2 + bias in fixup
        int g = batch[n];
        if (g == gb0) {
#pragma unroll
            for (int k = 0; k < 8; k++) atomicAdd(&spool[c0 + k], y[k]);
        } else {
#pragma unroll
            for (int k = 0; k < 8; k++) atomicAdd(&poolS[g * DFEAT + c0 + k], y[k]);
        }
    }
    __syncthreads();
    float pv = spool[t];
    if (pv != 0.f) atomicAdd(&poolS[gb0 * DFEAT + t], pv);
}

// ---------------- heads: block per graph; counts via binary search ---------------
__global__ __launch_bounds__(256) void heads_k(
        const float* __restrict__ xn, const int* __restrict__ target,
        const float* __restrict__ Wsh, const float* __restrict__ bsh,
        const float* __restrict__ Wnode,
        const float* __restrict__ Wtype, const float* __restrict__ btype,
        const float* __restrict__ Wcrit, const float* __restrict__ bcrit,
        const float* __restrict__ pool_sums, const int* __restrict__ batch,
        float* __restrict__ s2, float* __restrict__ out, int N) {
    __shared__ float gf[DFEAT];
    __shared__ float shm[DFEAT];
    __shared__ float part[8][6];
    __shared__ float cnt_sh;
    int b = blockIdx.x;
    int t = threadIdx.x;
    if (t == 0) {
        int lo = 0, hi = N;
        while (lo < hi) { int mid = (lo + hi) >> 1; if (batch[mid] < b) lo = mid + 1; else hi = mid; }
        int L = lo;
        lo = 0; hi = N;
        while (lo < hi) { int mid = (lo + hi) >> 1; if (batch[mid] < b + 1) lo = mid + 1; else hi = mid; }
        cnt_sh = (float)(lo - L);
    }
    __syncthreads();
    gf[t] = pool_sums[b * DFEAT + t] / fmaxf(cnt_sh, 1.f);
    __syncthreads();
    float acc = bsh[t];
    for (int k = 0; k < DFEAT; k++) acc += gf[k] * Wsh[k * DFEAT + t];
    shm[t] = fmaxf(acc, 0.f);
    __syncthreads();

    int tn = target[b];
    float xv = xn[(size_t)tn * DFEAT + t];
    float v[6];
    v[0] = shm[t] * Wnode[256 + t];
    v[1] = shm[t] * Wcrit[t];
#pragma unroll
    for (int a = 0; a < 4; a++)
        v[2 + a] = shm[t] * Wtype[t * 4 + a] + xv * Wtype[(256 + t) * 4 + a];
#pragma unroll
    for (int o = 16; o; o >>= 1)
#pragma unroll
        for (int i = 0; i < 6; i++) v[i] += __shfl_down_sync(0xffffffffu, v[i], o);
    if ((t & 31) == 0)
#pragma unroll
        for (int i = 0; i < 6; i++) part[t >> 5][i] = v[i];
    __syncthreads();
    if (t == 0) {
        float r[6] = {0.f, 0.f, 0.f, 0.f, 0.f, 0.f};
        for (int w = 0; w < 8; w++)
#pragma unroll
            for (int i = 0; i < 6; i++) r[i] += part[w][i];
        s2[b] = r[0];
        out[N + 32 + b] = r[1] + bcrit[0];
#pragma unroll
        for (int a = 0; a < 4; a++) out[N + b * 4 + a] = r[2 + a] + btype[a];
    }
}

// ---------------- fixup: add s2[batch] + bnode to node scores ----------------
__global__ void fixup_k(float* __restrict__ out, const int* __restrict__ batch,
                        const float* __restrict__ s2, const float* __restrict__ bnode, int N) {
    int i = blockIdx.x * 256 + threadIdx.x;
    if (i < N) out[i] += s2[batch[i]] + bnode[0];
}

// ---------------- host orchestration ----------------
extern "C" void kernel_launch(void* const* d_in, const int* in_sizes, int n_in,
                              void* d_out, int out_size) {
    const float* x      = (const float*)d_in[0];
    const int*   ei     = (const int*)d_in[1];
    const int*   batch  = (const int*)d_in[2];
    const int*   target = (const int*)d_in[3];
    const float* W1     = (const float*)d_in[4];
    const float* a1s    = (const float*)d_in[5];
    const float* a1d    = (const float*)d_in[6];
    const float* W2     = (const float*)d_in[8];
    const float* a2s    = (const float*)d_in[9];
    const float* a2d    = (const float*)d_in[10];
    const float* g1     = (const float*)d_in[12];
    const float* be1    = (const float*)d_in[13];
    const float* g2     = (const float*)d_in[14];
    const float* be2    = (const float*)d_in[15];
    const float* Wsh    = (const float*)d_in[16];
    const float* bsh    = (const float*)d_in[17];
    const float* Wnode  = (const float*)d_in[18];
    const float* bnode  = (const float*)d_in[19];
    const float* Wtype  = (const float*)d_in[20];
    const float* btype  = (const float*)d_in[21];
    const float* Wcrit  = (const float*)d_in[22];
    const float* bcrit  = (const float*)d_in[23];
    float* out = (float*)d_out;

    int N = in_sizes[2];
    int F = in_sizes[0] / N;
    int E = in_sizes[1] / 2;
    int Etot = E + N;

    float *bufA, *bufB, *als1, *ald1, *als2, *ald2;
    float *bnS, *bnQ, *sc1, *sh1, *sc2, *sh2, *poolS, *s2;
    int *cnt, *rowst, *cursor, *src_sorted;
    cudaGetSymbolAddress((void**)&bufA,  g_bufA);
    cudaGetSymbolAddress((void**)&bufB,  g_bufB);
    cudaGetSymbolAddress((void**)&als1,  g_als1);
    cudaGetSymbolAddress((void**)&ald1,  g_ald1);
    cudaGetSymbolAddress((void**)&als2,  g_als2);
    cudaGetSymbolAddress((void**)&ald2,  g_ald2);
    cudaGetSymbolAddress((void**)&cnt,   g_cnt);
    cudaGetSymbolAddress((void**)&rowst, g_rowst);
    cudaGetSymbolAddress((void**)&cursor, g_cursor);
    cudaGetSymbolAddress((void**)&src_sorted, g_src_sorted);
    cudaGetSymbolAddress((void**)&bnS,   g_bn_sum);
    cudaGetSymbolAddress((void**)&bnQ,   g_bn_sumsq);
    cudaGetSymbolAddress((void**)&sc1,   g_sc1);
    cudaGetSymbolAddress((void**)&sh1,   g_sh1);
    cudaGetSymbolAddress((void**)&sc2,   g_sc2);
    cudaGetSymbolAddress((void**)&sh2,   g_sh2);
    cudaGetSymbolAddress((void**)&poolS, g_pool_sum);
    cudaGetSymbolAddress((void**)&s2,    g_s2);

    // ---- zero init (async memsets; graph-capturable) ----
    cudaMemsetAsync(cnt,   0, (size_t)(N + 1) * sizeof(int));
    cudaMemsetAsync(als1,  0, (size_t)N * H1HEADS * sizeof(float));
    cudaMemsetAsync(ald1,  0, (size_t)N * H1HEADS * sizeof(float));
    cudaMemsetAsync(als2,  0, (size_t)N * sizeof(float));
    cudaMemsetAsync(ald2,  0, (size_t)N * sizeof(float));
    cudaMemsetAsync(poolS, 0, NGRAPHS * DFEAT * sizeof(float));
    cudaMemsetAsync(bnS,   0, DFEAT * sizeof(float));
    cudaMemsetAsync(bnQ,   0, DFEAT * sizeof(float));

    // ---- edge bucketing (shared by both layers) ----
    hist_k<<<cdiv(Etot, 256), 256>>>(ei, E, N, cnt);
    scan_k<<<1, SCAN_T>>>(cnt, rowst, N, Etot);
    cudaMemcpyAsync(cursor, rowst, (size_t)N * sizeof(int), cudaMemcpyDeviceToDevice);
    permute_k<<<cdiv(Etot, 256), 256>>>(ei, E, N, cursor, src_sorted);

    // ---- GAT layer 1: FFMA GEMM(+al1 epilogue) -> agg(+BN1 stats) ----
    {
        dim3 grid(DFEAT / 64, cdiv(N, TM));
        sgemm1_k<<<grid, 256>>>(x, W1, bufA, N, F, DFEAT, a1s, a1d, als1, ald1);
    }
    gat_agg1_k<<<cdiv(N, 8), 256>>>(rowst, src_sorted, bufA, als1, ald1, bufB, N, bnS, bnQ);
    bnprep_k<<<1, 256>>>(bnS, bnQ, g1, be1, sc1, sh1, N);

    // ---- GAT layer 2: tf32 MMA GEMM(BN1 on A, +al2) -> agg(+BN2 stats) ----
    {
        dim3 grid(DFEAT / 128, cdiv(N, 128));
        mma_gemm_k<true, true><<<grid, 256>>>(bufB, W2, bufA, N, DFEAT, DFEAT,
                                              sc1, sh1, a2s, a2d, als2, ald2);
    }
    cudaMemsetAsync(bnS, 0, DFEAT * sizeof(float));
    cudaMemsetAsync(bnQ, 0, DFEAT * sizeof(float));
    gat_agg2_k<<<cdiv(N, 8), 256>>>(rowst, src_sorted, bufA, als2, ald2, bufB, N, bnS, bnQ);
    bnprep_k<<<1, 256>>>(bnS, bnQ, g2, be2, sc2, sh2, N);

    // ---- BN2 apply + nodescore dot + pool accumulation ----
    bn2_node_pool_k<<<cdiv(N, 8), 256>>>(bufB, sc2, sh2, Wnode, batch, poolS, out, N);

    // ---- heads + fixup ----
    heads_k<<<NGRAPHS, 256>>>(bufB, target, Wsh, bsh, Wnode, Wtype, btype, Wcrit, bcrit,
                              poolS, batch, s2, out, N);
    fixup_k<<<cdiv(N, 256), 256>>>(out, batch, s2, bnode, N);
}